// round 5
// baseline (speedup 1.0000x reference)
#include <cuda_runtime.h>
#include <cuda_fp16.h>
#include <cstdint>
#include <cstring>

#define FH 38
#define FW 50
#define HW 1900
#define TAPS 15
#define NROIS 512
#define OUTDIM 490

#define S1 2
#define OCPAD1 256
#define OCPAD2 512

// ---------------- scratch (no allocation allowed) ----------------
__device__ float g_p1[2 * S1 * OCPAD1 * HW];   // conv1 partials [br][s][m][p]
__device__ float g_t0[OCPAD1 * HW];            // conv1 col-branch out (+bias)
__device__ float g_t1[OCPAD1 * HW];            // conv1 row-branch out (+bias)
__device__ float g_h0[OCPAD2 * HW];            // conv2 col-branch out
__device__ float g_h1[OCPAD2 * HW];            // conv2 row-branch out
__device__ float g_h [OUTDIM * HW];            // relu(h0+h1+biases)
__device__ float g_flat[NROIS * OUTDIM];
__device__ float g_fc1[NROIS * 2048];

// ---------------- helpers ----------------
__device__ __forceinline__ uint32_t h2pack(float lo, float hi) {
    const __half2 v = __floats2half2_rn(lo, hi);   // lo -> .x (low half)
    uint32_t r;
    memcpy(&r, &v, 4);
    return r;
}
__device__ __forceinline__ void mma16(float* c, const uint32_t* a, const uint32_t* b) {
    asm volatile("mma.sync.aligned.m16n8k16.row.col.f32.f16.f16.f32 "
        "{%0,%1,%2,%3}, {%4,%5,%6,%7}, {%8,%9}, {%0,%1,%2,%3};"
        : "+f"(c[0]), "+f"(c[1]), "+f"(c[2]), "+f"(c[3])
        : "r"(a[0]), "r"(a[1]), "r"(a[2]), "r"(a[3]), "r"(b[0]), "r"(b[1]));
}

// ---------------- packed f32x2 helpers (FC path) ----------------
__device__ __forceinline__ void ffma2u(unsigned long long &d, unsigned long long a, unsigned long long b) {
    asm("fma.rn.f32x2 %0, %1, %2, %0;" : "+l"(d) : "l"(a), "l"(b));
}
__device__ __forceinline__ unsigned long long bcast2(float x) {
    unsigned long long r;
    asm("mov.b64 %0, {%1, %1};" : "=l"(r) : "f"(x));
    return r;
}
__device__ __forceinline__ float2 unpack2(unsigned long long v) {
    float2 r;
    asm("mov.b64 {%0, %1}, %2;" : "=f"(r.x), "=f"(r.y) : "l"(v));
    return r;
}

// ============ fp16 mma.sync m16n8k16 implicit-GEMM separable conv ============
// D[m=OC, n=spatial] = sum_k W[m,k] * Im2col[n,k]
//   k -> (c = k/15, t = k%15), d = t-7
//   shiftH: val = in[c*HW + p + d*FW]  if 0 <= p + d*FW < HW
//   shiftW: val = in[c*HW + p + d]     if 0 <= (p%FW) + d < FW
#define CM 128
#define CN 128
#define CK 32        // k elements per stage (16 half2 words)
#define CWP 20       // word stride: 16 data words + 4 pad -> conflict-free frags

__global__ __launch_bounds__(256, 1) void conv_mma(
    const float* __restrict__ in0, const float* __restrict__ w0, float* __restrict__ po0,
    const float* __restrict__ in1, const float* __restrict__ w1, float* __restrict__ po1,
    int sh0, int sh1, int Ktot, int OC, int OCpad, int S)
{
    __shared__ __align__(16) uint32_t As[CM][CWP];   // [m][kword] half2
    __shared__ __align__(16) uint32_t Bs[CN][CWP];   // [n][kword] half2

    const int z = blockIdx.z;
    const int br = z / S, s = z % S;
    const float* in  = br ? in1 : in0;
    const float* wgt = br ? w1 : w0;
    float* pout = (br ? po1 : po0) + (size_t)s * OCpad * HW;
    const int shiftH = br ? sh1 : sh0;
    const int m0 = blockIdx.y * CM;
    const int p0 = blockIdx.x * CN;
    const int Kc = Ktot / S;
    const int kb0 = s * Kc;
    const int nit = Kc / CK;

    const int tid  = threadIdx.x;
    const int lane = tid & 31;
    const int wid  = tid >> 5;
    const int wm = (wid >> 2) * 64;   // warp M offset (0 / 64)
    const int wn = (wid & 3) * 32;    // warp N offset (0/32/64/96)
    const int lg = lane >> 2;         // group 0..7
    const int lt = lane & 3;          // 0..3

    // loader: each thread owns one row and 16 consecutive k elements (8 words)
    const int lr  = tid >> 1;
    const int lk  = (tid & 1) * 16;   // k-element offset
    const int lkw = (tid & 1) * 8;    // word offset
    const int lp  = p0 + lr;
    const int lj  = lp % FW;

    float acc[4][4][4];
#pragma unroll
    for (int mi = 0; mi < 4; mi++)
#pragma unroll
        for (int ni = 0; ni < 4; ni++)
#pragma unroll
            for (int q = 0; q < 4; q++) acc[mi][ni][q] = 0.f;

    uint32_t aR[8], bR[8];

    auto loadG = [&](int it) {
        const int kb = kb0 + it * CK + lk;
        // A: weights (row-major [OC][Ktot])
        if (m0 + lr < OC) {
            const float* wp = wgt + (size_t)(m0 + lr) * Ktot + kb;
#pragma unroll
            for (int q = 0; q < 4; q++) {
                const float4 w4 = *(const float4*)(wp + q * 4);
                aR[q * 2 + 0] = h2pack(w4.x, w4.y);
                aR[q * 2 + 1] = h2pack(w4.z, w4.w);
            }
        } else {
#pragma unroll
            for (int q = 0; q < 8; q++) aR[q] = 0u;
        }
        // B: im2col
        float bv[16];
        if (shiftH) {
#pragma unroll
            for (int e = 0; e < 16; e++) {
                const int kg = kb + e;
                const int c = kg / TAPS;
                const int d = kg - c * TAPS - 7;
                const int pp = lp + d * FW;
                bv[e] = (lp < HW && pp >= 0 && pp < HW) ? in[(size_t)c * HW + pp] : 0.f;
            }
        } else {
#pragma unroll
            for (int e = 0; e < 16; e++) {
                const int kg = kb + e;
                const int c = kg / TAPS;
                const int d = kg - c * TAPS - 7;
                const int jj = lj + d;
                bv[e] = (lp < HW && jj >= 0 && jj < FW) ? in[(size_t)c * HW + lp + d] : 0.f;
            }
        }
#pragma unroll
        for (int q = 0; q < 8; q++) bR[q] = h2pack(bv[2 * q], bv[2 * q + 1]);
    };

    auto storeS = [&]() {
        *(uint4*)&As[lr][lkw]     = make_uint4(aR[0], aR[1], aR[2], aR[3]);
        *(uint4*)&As[lr][lkw + 4] = make_uint4(aR[4], aR[5], aR[6], aR[7]);
        *(uint4*)&Bs[lr][lkw]     = make_uint4(bR[0], bR[1], bR[2], bR[3]);
        *(uint4*)&Bs[lr][lkw + 4] = make_uint4(bR[4], bR[5], bR[6], bR[7]);
    };

    loadG(0);
    storeS();
    __syncthreads();

    for (int it = 0; it < nit; ++it) {
        if (it + 1 < nit) loadG(it + 1);   // overlap global loads with MMA
#pragma unroll
        for (int ks = 0; ks < 2; ks++) {   // two k16 steps per stage
            const int kw = ks * 8;
            uint32_t af[4][4], bf[4][2];
#pragma unroll
            for (int mi = 0; mi < 4; mi++) {
                const int r = wm + mi * 16 + lg;
                af[mi][0] = As[r][kw + lt];
                af[mi][1] = As[r + 8][kw + lt];
                af[mi][2] = As[r][kw + 4 + lt];
                af[mi][3] = As[r + 8][kw + 4 + lt];
            }
#pragma unroll
            for (int ni = 0; ni < 4; ni++) {
                const int cidx = wn + ni * 8 + lg;
                bf[ni][0] = Bs[cidx][kw + lt];
                bf[ni][1] = Bs[cidx][kw + 4 + lt];
            }
#pragma unroll
            for (int mi = 0; mi < 4; mi++)
#pragma unroll
                for (int ni = 0; ni < 4; ni++)
                    mma16(acc[mi][ni], af[mi], bf[ni]);
        }
        __syncthreads();
        if (it + 1 < nit) { storeS(); __syncthreads(); }
    }

    // epilogue: c0,c1 at (row, col..col+1), c2,c3 at (row+8, ...)
#pragma unroll
    for (int mi = 0; mi < 4; mi++) {
        const int r0 = m0 + wm + mi * 16 + lg;
#pragma unroll
        for (int ni = 0; ni < 4; ni++) {
            const int cc = p0 + wn + ni * 8 + 2 * lt;
            if (cc < HW) {   // cc even, HW even -> pair safe
                if (r0 < OC)
                    *(float2*)&pout[(size_t)r0 * HW + cc] = make_float2(acc[mi][ni][0], acc[mi][ni][1]);
                if (r0 + 8 < OC)
                    *(float2*)&pout[(size_t)(r0 + 8) * HW + cc] = make_float2(acc[mi][ni][2], acc[mi][ni][3]);
            }
        }
    }
}

// ---------------- combine conv1 partials + bias ----------------
__global__ void combine1(const float4* __restrict__ part, const float* __restrict__ b0,
                         const float* __restrict__ b1, float4* __restrict__ t0, float4* __restrict__ t1)
{
    const int NP = HW / 4;
    const int idx = blockIdx.x * blockDim.x + threadIdx.x;
    if (idx >= 2 * OCPAD1 * NP) return;
    const int b = idx / (OCPAD1 * NP);
    const int r = idx - b * OCPAD1 * NP;
    const int m = r / NP;
    const float4* base = part + (size_t)(b * S1) * OCPAD1 * NP + r;
    float4 acc = base[0];
#pragma unroll
    for (int ss = 1; ss < S1; ss++) {
        const float4 v = base[(size_t)ss * OCPAD1 * NP];
        acc.x += v.x; acc.y += v.y; acc.z += v.z; acc.w += v.w;
    }
    const float bv = (b ? b1 : b0)[m];
    acc.x += bv; acc.y += bv; acc.z += bv; acc.w += bv;
    (b ? t1 : t0)[r] = acc;
}

// ---------------- combine conv2 branches + biases + relu ----------------
__global__ void combine2(const float4* __restrict__ h0, const float4* __restrict__ h1,
                         const float* __restrict__ bc, const float* __restrict__ brr,
                         float4* __restrict__ h)
{
    const int NP = HW / 4;
    const int idx = blockIdx.x * blockDim.x + threadIdx.x;
    if (idx >= OUTDIM * NP) return;
    const int m = idx / NP;
    const float4 a = h0[idx];
    const float4 b = h1[idx];
    const float bv = bc[m] + brr[m];
    float4 o;
    o.x = fmaxf(a.x + b.x + bv, 0.f);
    o.y = fmaxf(a.y + b.y + bv, 0.f);
    o.z = fmaxf(a.z + b.z + bv, 0.f);
    o.w = fmaxf(a.w + b.w + bv, 0.f);
    h[idx] = o;
}

// ---------------- ROI bilinear max pool ----------------
__global__ void roi_pool(const float* __restrict__ h, const float* __restrict__ rois,
                         float* __restrict__ flat)
{
    const int idx = blockIdx.x * blockDim.x + threadIdx.x;
    if (idx >= NROIS * OUTDIM) return;
    const int n  = idx / OUTDIM;
    const int ch = idx - n * OUTDIM;
    const int bin = ch / 10;
    const int bi  = bin / 7;
    const int bj  = bin - bi * 7;

    const float4 r = ((const float4*)rois)[n];
    const float xmin = (r.x * 0.0625f) / 50.f;
    const float ymin = (r.y * 0.0625f) / 38.f;
    const float xmax = (r.z * 0.0625f) / 50.f;
    const float ymax = (r.w * 0.0625f) / 38.f;
    const float stx = (xmax - xmin) / 7.f;
    const float sty = (ymax - ymin) / 7.f;

    const float* f = h + (size_t)ch * HW;
    float best = -3.4e38f;
#pragma unroll
    for (int ky = 0; ky < 2; ky++) {
        const float yy = (ymin + (float)(bi + ky) * sty) * 37.f;
        const float fy = floorf(yy);
        const float wy = yy - fy;
        const int y0 = (int)fminf(fmaxf(fy, 0.f), 37.f);
        const int y1 = (int)fminf(fmaxf(fy + 1.f, 0.f), 37.f);
#pragma unroll
        for (int kx = 0; kx < 2; kx++) {
            const float xx = (xmin + (float)(bj + kx) * stx) * 49.f;
            const float fx = floorf(xx);
            const float wx = xx - fx;
            const int x0 = (int)fminf(fmaxf(fx, 0.f), 49.f);
            const int x1 = (int)fminf(fmaxf(fx + 1.f, 0.f), 49.f);
            const float v00 = f[y0 * FW + x0];
            const float v01 = f[y0 * FW + x1];
            const float v10 = f[y1 * FW + x0];
            const float v11 = f[y1 * FW + x1];
            const float top = v00 + (v01 - v00) * wx;
            const float bot = v10 + (v11 - v10) * wx;
            const float val = top + (bot - top) * wy;
            best = fmaxf(best, val);
        }
    }
    flat[idx] = best;
}

// ---------------- GEMM: C[M,N] = A[M,K] * B[N,K]^T + bias (optional relu) ----------------
#define GBM 64
#define GBN 64
#define GBK 16

__global__ __launch_bounds__(128, 1) void gemm_tn(
    const float* __restrict__ A, const float* __restrict__ B,
    const float* __restrict__ bias, float* __restrict__ C,
    int M, int N, int K, int ldc, int relu)
{
    const int m0 = blockIdx.y * GBM;
    const int n0 = blockIdx.x * GBN;
    const int nit = (K + GBK - 1) / GBK;

    __shared__ __align__(16) float As[GBK][GBM + 4];
    __shared__ __align__(16) float Bs[GBK][GBN + 4];

    const int tid = threadIdx.x;
    const int tx = tid & 15;
    const int ty = tid >> 4;

    const int lr  = tid >> 1;
    const int lkq = (tid & 1) * 8;

    unsigned long long acc[8][2];
#pragma unroll
    for (int i = 0; i < 8; i++) { acc[i][0] = 0ull; acc[i][1] = 0ull; }

    for (int it = 0; it < nit; ++it) {
        const int k0 = it * GBK;
        {
            const int m = m0 + lr;
            const float* p = A + (size_t)m * K + k0 + lkq;
#pragma unroll
            for (int q = 0; q < 8; q++) {
                const int k = k0 + lkq + q;
                As[lkq + q][lr] = (m < M && k < K) ? __ldg(p + q) : 0.f;
            }
        }
        {
            const int nn = n0 + lr;
            const float* p = B + (size_t)nn * K + k0 + lkq;
#pragma unroll
            for (int q = 0; q < 8; q++) {
                const int k = k0 + lkq + q;
                Bs[lkq + q][lr] = (nn < N && k < K) ? __ldg(p + q) : 0.f;
            }
        }
        __syncthreads();
#pragma unroll
        for (int kk = 0; kk < GBK; kk++) {
            const float4 a0 = *(const float4*)&As[kk][ty * 8];
            const float4 a1 = *(const float4*)&As[kk][ty * 8 + 4];
            const ulonglong2 bv = *(const ulonglong2*)&Bs[kk][tx * 4];
            const float a[8] = { a0.x, a0.y, a0.z, a0.w, a1.x, a1.y, a1.z, a1.w };
#pragma unroll
            for (int mi = 0; mi < 8; mi++) {
                const unsigned long long av = bcast2(a[mi]);
                ffma2u(acc[mi][0], av, bv.x);
                ffma2u(acc[mi][1], av, bv.y);
            }
        }
        __syncthreads();
    }

#pragma unroll
    for (int mi = 0; mi < 8; mi++) {
        const int m = m0 + ty * 8 + mi;
        if (m >= M) continue;
        float* crow = C + (size_t)m * ldc;
#pragma unroll
        for (int nj = 0; nj < 2; nj++) {
            const float2 v = unpack2(acc[mi][nj]);
            const int n = n0 + tx * 4 + nj * 2;
            if (n < N) {
                float o = v.x + bias[n];
                if (relu) o = o > 0.f ? o : 0.f;
                crow[n] = o;
            }
            if (n + 1 < N) {
                float o = v.y + bias[n + 1];
                if (relu) o = o > 0.f ? o : 0.f;
                crow[n + 1] = o;
            }
        }
    }
}

// ---------------- launch ----------------
extern "C" void kernel_launch(void* const* d_in, const int* in_sizes, int n_in,
                              void* d_out, int out_size)
{
    const float* x          = (const float*)d_in[0];
    const float* rois       = (const float*)d_in[1];
    const float* w_col_max  = (const float*)d_in[2];
    const float* b_col_max  = (const float*)d_in[3];
    const float* w_col      = (const float*)d_in[4];
    const float* b_col      = (const float*)d_in[5];
    const float* w_row_max  = (const float*)d_in[6];
    const float* b_row_max  = (const float*)d_in[7];
    const float* w_row      = (const float*)d_in[8];
    const float* b_row      = (const float*)d_in[9];
    const float* w_fc1      = (const float*)d_in[10];
    const float* b_fc1      = (const float*)d_in[11];
    const float* w_score    = (const float*)d_in[12];
    const float* b_score    = (const float*)d_in[13];
    const float* w_loc      = (const float*)d_in[14];
    const float* b_loc      = (const float*)d_in[15];
    float* out = (float*)d_out;

    float *p1, *t0, *t1, *h0, *h1, *h, *flat, *fc1;
    cudaGetSymbolAddress((void**)&p1,   g_p1);
    cudaGetSymbolAddress((void**)&t0,   g_t0);
    cudaGetSymbolAddress((void**)&t1,   g_t1);
    cudaGetSymbolAddress((void**)&h0,   g_h0);
    cudaGetSymbolAddress((void**)&h1,   g_h1);
    cudaGetSymbolAddress((void**)&h,    g_h);
    cudaGetSymbolAddress((void**)&flat, g_flat);
    cudaGetSymbolAddress((void**)&fc1,  g_fc1);

    // conv1: x(2048ch). branch0: w_col_max 15x1 (H-shift), branch1: w_row_max 1x15 (W-shift)
    {
        dim3 grid((HW + CN - 1) / CN, OCPAD1 / CM, 2 * S1);   // 15 x 2 x 4 = 120 CTAs
        conv_mma<<<grid, 256>>>(
            x, w_col_max, p1,
            x, w_row_max, p1 + (size_t)S1 * OCPAD1 * HW,
            1, 0, 2048 * TAPS, 256, OCPAD1, S1);
    }
    // t0/t1 = sum partials + bias
    {
        const int n = 2 * OCPAD1 * (HW / 4);
        combine1<<<(n + 255) / 256, 256>>>((const float4*)p1, b_col_max, b_row_max,
                                           (float4*)t0, (float4*)t1);
    }
    // conv2: branch0: t0 with w_col 1x15 (W-shift), branch1: t1 with w_row 15x1 (H-shift)
    {
        dim3 grid((HW + CN - 1) / CN, OCPAD2 / CM, 2);        // 15 x 4 x 2 = 120 CTAs
        conv_mma<<<grid, 256>>>(
            t0, w_col, h0,
            t1, w_row, h1,
            0, 1, 256 * TAPS, OUTDIM, OCPAD2, 1);
    }
    // h = relu(h0 + h1 + b_col + b_row)
    {
        const int n = OUTDIM * (HW / 4);
        combine2<<<(n + 255) / 256, 256>>>((const float4*)h0, (const float4*)h1, b_col, b_row, (float4*)h);
    }
    // ROI pool -> flat [512, 490]
    {
        const int n = NROIS * OUTDIM;
        roi_pool<<<(n + 255) / 256, 256>>>(h, rois, flat);
    }
    // fc1 = relu(flat @ w_fc1^T + b_fc1)   [512, 2048]
    {
        dim3 grid(2048 / GBN, NROIS / GBM);
        gemm_tn<<<grid, 128>>>(flat, w_fc1, b_fc1, fc1, NROIS, 2048, OUTDIM, 2048, 1);
    }
    // roi_cls_locs = fc1 @ w_loc^T + b_loc   [512, 324]
    {
        dim3 grid((324 + GBN - 1) / GBN, NROIS / GBM);
        gemm_tn<<<grid, 128>>>(fc1, w_loc, b_loc, out, NROIS, 324, 2048, 324, 0);
    }
    // roi_scores = fc1 @ w_score^T + b_score [512, 81]
    {
        dim3 grid((81 + GBN - 1) / GBN, NROIS / GBM);
        gemm_tn<<<grid, 128>>>(fc1, w_score, b_score, out + NROIS * 324, NROIS, 81, 2048, 81, 0);
    }
}

// round 6
// speedup vs baseline: 1.5612x; 1.5612x over previous
#include <cuda_runtime.h>
#include <cuda_fp16.h>
#include <cstdint>
#include <cstring>

#define FH 38
#define FW 50
#define HW 1900
#define TAPS 15
#define NROIS 512
#define OUTDIM 490

#define S1 2
#define OCPAD1 256
#define OCPAD2 512
#define PROWS 3392            // padded rows: covers (i+7)*64+(j+7)+/-448 incl. guard tiles

// ---------------- scratch (no allocation allowed) ----------------
__device__ __half g_XP [PROWS * 2048];            // padded x, spatial-major, c contiguous
__device__ __half g_TP0[PROWS * 256];             // conv2 branch0 input (t0), padded
__device__ __half g_TP1[PROWS * 256];             // conv2 branch1 input (t1), padded
__device__ __half g_wt1[2 * TAPS * OCPAD1 * 2048];// conv1 weights [br][t][oc][c]
__device__ __half g_wt2[2 * TAPS * OCPAD2 * 256]; // conv2 weights
__device__ float  g_p1[2 * S1 * OCPAD1 * HW];     // conv1 partials [br][s][oc][p]
__device__ float  g_h0[OCPAD2 * HW];
__device__ float  g_h1[OCPAD2 * HW];
__device__ float  g_h [OUTDIM * HW];
__device__ float  g_flat[NROIS * OUTDIM];
__device__ float  g_fc1[NROIS * 2048];

// ---------------- PTX helpers ----------------
__device__ __forceinline__ uint32_t smem_u32(const void* p) {
    uint32_t a;
    asm("{ .reg .u64 t; cvta.to.shared.u64 t, %1; cvt.u32.u64 %0, t; }" : "=r"(a) : "l"(p));
    return a;
}
__device__ __forceinline__ void cp16(uint32_t dst, const __half* src) {
    asm volatile("cp.async.cg.shared.global [%0], [%1], 16;"
                 :: "r"(dst), "l"(__cvta_generic_to_global(src)));
}
__device__ __forceinline__ void cp_commit() {
    asm volatile("cp.async.commit_group;" ::: "memory");
}
template<int N> __device__ __forceinline__ void cp_wait() {
    asm volatile("cp.async.wait_group %0;" :: "n"(N) : "memory");
}
__device__ __forceinline__ void ldsm4(uint32_t* r, uint32_t addr) {
    asm volatile("ldmatrix.sync.aligned.m8n8.x4.shared.b16 {%0,%1,%2,%3}, [%4];"
        : "=r"(r[0]), "=r"(r[1]), "=r"(r[2]), "=r"(r[3]) : "r"(addr));
}
__device__ __forceinline__ void mma16(float* c, const uint32_t* a, const uint32_t* b) {
    asm volatile("mma.sync.aligned.m16n8k16.row.col.f32.f16.f16.f32 "
        "{%0,%1,%2,%3}, {%4,%5,%6,%7}, {%8,%9}, {%0,%1,%2,%3};"
        : "+f"(c[0]), "+f"(c[1]), "+f"(c[2]), "+f"(c[3])
        : "r"(a[0]), "r"(a[1]), "r"(a[2]), "r"(a[3]), "r"(b[0]), "r"(b[1]));
}
// FC path (f32x2)
__device__ __forceinline__ void ffma2u(unsigned long long &d, unsigned long long a, unsigned long long b) {
    asm("fma.rn.f32x2 %0, %1, %2, %0;" : "+l"(d) : "l"(a), "l"(b));
}
__device__ __forceinline__ unsigned long long bcast2(float x) {
    unsigned long long r;
    asm("mov.b64 %0, {%1, %1};" : "=l"(r) : "f"(x));
    return r;
}
__device__ __forceinline__ float2 unpack2(unsigned long long v) {
    float2 r;
    asm("mov.b64 {%0, %1}, %2;" : "=f"(r.x), "=f"(r.y) : "l"(v));
    return r;
}

// ---------------- prep: zero the padded buffers ----------------
__global__ void zero_fill(uint4* a, int na, uint4* b, int nb, uint4* c, int nc) {
    const int i = blockIdx.x * blockDim.x + threadIdx.x;
    const uint4 z = make_uint4(0, 0, 0, 0);
    if (i < na) a[i] = z;
    if (i < nb) b[i] = z;
    if (i < nc) c[i] = z;
}

// ---------------- prep: x [2048][1900] f32 -> XP [(i+7)*64+j+7][2048] half ----------------
__global__ __launch_bounds__(256) void xpose(const float* __restrict__ x, __half2* __restrict__ XP)
{
    __shared__ float s[64][65];
    const int c0 = blockIdx.x * 64, p0 = blockIdx.y * 64;
    const int tid = threadIdx.x;
    const int r = tid >> 2, q0 = (tid & 3) * 16;
#pragma unroll
    for (int q = 0; q < 16; q++) {
        const int p = p0 + q0 + q;
        s[r][q0 + q] = (p < HW) ? x[(size_t)(c0 + r) * HW + p] : 0.f;
    }
    __syncthreads();
#pragma unroll
    for (int k = 0; k < 8; k++) {
        const int widx = tid + k * 256;
        const int pl = widx >> 5, cp = widx & 31;
        const int p = p0 + pl;
        if (p < HW) {
            const int i = p / FW, j = p - i * FW;
            const int row = (i + 7) * 64 + j + 7;
            XP[(size_t)row * 1024 + (c0 >> 1) + cp] = __floats2half2_rn(s[2 * cp][pl], s[2 * cp + 1][pl]);
        }
    }
}

// ---------------- prep: w [oc][ic][15] f32 -> wt [t][ocpad][ic] half ----------------
__global__ __launch_bounds__(256) void wtrans(const float* __restrict__ w, __half* __restrict__ wt,
                                              int OC, int OCpad, int IC)
{
    __shared__ float s[128 * TAPS];
    const int m = blockIdx.x, c0 = blockIdx.y * 128;
    const int tid = threadIdx.x;
    if (m < OC) {
        const float* src = w + ((size_t)m * IC + c0) * TAPS;
        for (int i = tid; i < 128 * TAPS; i += 256) s[i] = src[i];
    } else {
        for (int i = tid; i < 128 * TAPS; i += 256) s[i] = 0.f;
    }
    __syncthreads();
    for (int i = tid; i < 128 * TAPS; i += 256) {
        const int t = i >> 7, ci = i & 127;
        wt[((size_t)t * OCpad + m) * IC + c0 + ci] = __float2half(s[ci * TAPS + t]);
    }
}

// ============ tap-decomposed fp16 GEMM conv: cp.async 3-stage + ldmatrix ============
// D[oc][p] = sum_t sum_c wt[t][oc][c] * P[qbase(p) + (t-7)*step][c]
#define NSTG 3
#define APITCH 80                 // 64B data + 16B pad: ldmatrix conflict-free
#define TILEB (128 * APITCH)      // 10240 B
#define STAGEB (2 * TILEB)
#define CONV_SMEM (NSTG * STAGEB) // 61440 B

__global__ __launch_bounds__(256, 1) void conv_mma(
    const __half* __restrict__ inB0, const __half* __restrict__ inB1,
    const __half* __restrict__ wA0,  const __half* __restrict__ wA1,
    float* __restrict__ out0, float* __restrict__ out1,
    int step0, int step1, int ICfull, int icChunks, int OCpad, int S)
{
    extern __shared__ __align__(16) char smem[];
    const int z = blockIdx.z;
    const int br = z / S, s = z % S;
    const __half* inB = br ? inB1 : inB0;
    const __half* wA  = br ? wA1  : wA0;
    float* out = (br ? out1 : out0) + (size_t)s * OCpad * HW;
    const int step = br ? step1 : step0;
    const int m0 = blockIdx.y * 128;
    const int p0 = blockIdx.x * 128;
    const int icOff = s * icChunks * 32;
    const int nit = TAPS * icChunks;

    const int tid = threadIdx.x;
    const int lane = tid & 31, wid = tid >> 5;
    const int wm = (wid >> 2) * 64, wn = (wid & 3) * 32;
    const int lg = lane >> 2, lt = lane & 3;
    const uint32_t sbase = smem_u32(smem);

    // loader: each thread owns one row (0..127) and one 32B half of the 64B chunk row
    const int lrow = tid >> 1, lseg = tid & 1;
    const int lp = p0 + lrow;
    const int li = lp / FW, lj = lp - li * FW;
    const int qbase = (li + 7) * 64 + lj + 7;
    const __half* aBase = wA + (size_t)(m0 + lrow) * ICfull + icOff + lseg * 16;
    const __half* bBase = inB + (size_t)qbase * ICfull + icOff + lseg * 16;
    const size_t aTapStride = (size_t)OCpad * ICfull;
    const long  bTapStride = (long)step * ICfull;
    const uint32_t aDstOff = (uint32_t)(lrow * APITCH + lseg * 32);
    const uint32_t bDstOff = aDstOff + TILEB;

    // ldmatrix lane addressing
    const uint32_t aLane = (uint32_t)((wm + (lane & 7) + ((lane >> 3) & 1) * 8) * APITCH + ((lane >> 4) & 1) * 16);
    const uint32_t bLane = (uint32_t)(TILEB + (wn + (lane & 7) + ((lane >> 4) & 1) * 8) * APITCH + ((lane >> 3) & 1) * 16);

    float acc[4][4][4];
#pragma unroll
    for (int mi = 0; mi < 4; mi++)
#pragma unroll
        for (int ni = 0; ni < 4; ni++)
#pragma unroll
            for (int q = 0; q < 4; q++) acc[mi][ni][q] = 0.f;

    int ti = 0, ci = 0;   // issue cursor: tap, channel-chunk
    auto issue = [&](int st) {
        const uint32_t buf = sbase + (st % NSTG) * STAGEB;
        const __half* aS = aBase + (size_t)ti * aTapStride + ci * 32;
        const __half* bS = bBase + (long)(ti - 7) * bTapStride + ci * 32;
        cp16(buf + aDstOff, aS); cp16(buf + aDstOff + 16, aS + 8);
        cp16(buf + bDstOff, bS); cp16(buf + bDstOff + 16, bS + 8);
        cp_commit();
        if (++ci == icChunks) { ci = 0; ++ti; }
    };

    issue(0); issue(1); issue(2);

    for (int it = 0; it < nit; ++it) {
        const int rem = nit - 1 - it;
        if (rem >= 2) cp_wait<2>();
        else if (rem == 1) cp_wait<1>();
        else cp_wait<0>();
        __syncthreads();

        const uint32_t buf = sbase + (it % NSTG) * STAGEB;
#pragma unroll
        for (int ks = 0; ks < 2; ks++) {
            uint32_t af[4][4], bf[4][2];
#pragma unroll
            for (int mi = 0; mi < 4; mi++)
                ldsm4(af[mi], buf + aLane + mi * (16 * APITCH) + ks * 32);
#pragma unroll
            for (int pr = 0; pr < 2; pr++) {
                uint32_t r[4];
                ldsm4(r, buf + bLane + pr * (16 * APITCH) + ks * 32);
                bf[pr * 2][0] = r[0]; bf[pr * 2][1] = r[1];
                bf[pr * 2 + 1][0] = r[2]; bf[pr * 2 + 1][1] = r[3];
            }
#pragma unroll
            for (int mi = 0; mi < 4; mi++)
#pragma unroll
                for (int ni = 0; ni < 4; ni++)
                    mma16(acc[mi][ni], af[mi], bf[ni]);
        }
        __syncthreads();
        if (it + 3 < nit) issue(it + 3);
    }

    // epilogue: D rows = oc, cols = real spatial p
#pragma unroll
    for (int mi = 0; mi < 4; mi++) {
        const int r0 = m0 + wm + mi * 16 + lg;
#pragma unroll
        for (int ni = 0; ni < 4; ni++) {
            const int cc = p0 + wn + ni * 8 + 2 * lt;
            if (cc < HW) {   // cc even, HW even -> pair safe
                *(float2*)&out[(size_t)r0 * HW + cc] = make_float2(acc[mi][ni][0], acc[mi][ni][1]);
                *(float2*)&out[(size_t)(r0 + 8) * HW + cc] = make_float2(acc[mi][ni][2], acc[mi][ni][3]);
            }
        }
    }
}

// ---------------- combine1: sum conv1 splits + bias -> padded half inputs for conv2 ----------------
__global__ __launch_bounds__(256) void combine1(const float* __restrict__ p1,
                                                const float* __restrict__ b0, const float* __restrict__ b1,
                                                __half2* __restrict__ TP0, __half2* __restrict__ TP1)
{
    __shared__ float s[64][65];
    const int b = blockIdx.z;
    const int m0 = blockIdx.x * 64, p0 = blockIdx.y * 64;
    const int tid = threadIdx.x;
    const float* base = p1 + (size_t)b * (S1 * OCPAD1 * HW);
    const int r = tid >> 2, q0 = (tid & 3) * 16;
#pragma unroll
    for (int q = 0; q < 16; q++) {
        const int p = p0 + q0 + q;
        s[r][q0 + q] = (p < HW)
            ? base[(size_t)(m0 + r) * HW + p] + base[(size_t)OCPAD1 * HW + (size_t)(m0 + r) * HW + p]
            : 0.f;
    }
    __syncthreads();
    const float* bias = b ? b1 : b0;
    __half2* TP = b ? TP1 : TP0;
#pragma unroll
    for (int k = 0; k < 8; k++) {
        const int widx = tid + k * 256;
        const int pl = widx >> 5, cp = widx & 31;
        const int p = p0 + pl;
        if (p < HW) {
            const int i = p / FW, j = p - i * FW;
            const int row = (i + 7) * 64 + j + 7;
            const float vx = s[2 * cp][pl] + bias[m0 + 2 * cp];
            const float vy = s[2 * cp + 1][pl] + bias[m0 + 2 * cp + 1];
            TP[(size_t)row * 128 + (m0 >> 1) + cp] = __floats2half2_rn(vx, vy);
        }
    }
}

// ---------------- combine2: h = relu(h0 + h1 + biases) ----------------
__global__ void combine2(const float4* __restrict__ h0, const float4* __restrict__ h1,
                         const float* __restrict__ bc, const float* __restrict__ brr,
                         float4* __restrict__ h)
{
    const int NP = HW / 4;
    const int idx = blockIdx.x * blockDim.x + threadIdx.x;
    if (idx >= OUTDIM * NP) return;
    const int m = idx / NP;
    const float4 a = h0[idx];
    const float4 b = h1[idx];
    const float bv = bc[m] + brr[m];
    float4 o;
    o.x = fmaxf(a.x + b.x + bv, 0.f);
    o.y = fmaxf(a.y + b.y + bv, 0.f);
    o.z = fmaxf(a.z + b.z + bv, 0.f);
    o.w = fmaxf(a.w + b.w + bv, 0.f);
    h[idx] = o;
}

// ---------------- ROI bilinear max pool ----------------
__global__ void roi_pool(const float* __restrict__ h, const float* __restrict__ rois,
                         float* __restrict__ flat)
{
    const int idx = blockIdx.x * blockDim.x + threadIdx.x;
    if (idx >= NROIS * OUTDIM) return;
    const int n  = idx / OUTDIM;
    const int ch = idx - n * OUTDIM;
    const int bin = ch / 10;
    const int bi  = bin / 7;
    const int bj  = bin - bi * 7;

    const float4 r = ((const float4*)rois)[n];
    const float xmin = (r.x * 0.0625f) / 50.f;
    const float ymin = (r.y * 0.0625f) / 38.f;
    const float xmax = (r.z * 0.0625f) / 50.f;
    const float ymax = (r.w * 0.0625f) / 38.f;
    const float stx = (xmax - xmin) / 7.f;
    const float sty = (ymax - ymin) / 7.f;

    const float* f = h + (size_t)ch * HW;
    float best = -3.4e38f;
#pragma unroll
    for (int ky = 0; ky < 2; ky++) {
        const float yy = (ymin + (float)(bi + ky) * sty) * 37.f;
        const float fy = floorf(yy);
        const float wy = yy - fy;
        const int y0 = (int)fminf(fmaxf(fy, 0.f), 37.f);
        const int y1 = (int)fminf(fmaxf(fy + 1.f, 0.f), 37.f);
#pragma unroll
        for (int kx = 0; kx < 2; kx++) {
            const float xx = (xmin + (float)(bj + kx) * stx) * 49.f;
            const float fx = floorf(xx);
            const float wx = xx - fx;
            const int x0 = (int)fminf(fmaxf(fx, 0.f), 49.f);
            const int x1 = (int)fminf(fmaxf(fx + 1.f, 0.f), 49.f);
            const float v00 = f[y0 * FW + x0];
            const float v01 = f[y0 * FW + x1];
            const float v10 = f[y1 * FW + x0];
            const float v11 = f[y1 * FW + x1];
            const float top = v00 + (v01 - v00) * wx;
            const float bot = v10 + (v11 - v10) * wx;
            const float val = top + (bot - top) * wy;
            best = fmaxf(best, val);
        }
    }
    flat[idx] = best;
}

// ---------------- GEMM: C[M,N] = A[M,K] * B[N,K]^T + bias (optional relu) ----------------
#define GBM 64
#define GBN 64
#define GBK 16

__global__ __launch_bounds__(128, 1) void gemm_tn(
    const float* __restrict__ A, const float* __restrict__ B,
    const float* __restrict__ bias, float* __restrict__ C,
    int M, int N, int K, int ldc, int relu)
{
    const int m0 = blockIdx.y * GBM;
    const int n0 = blockIdx.x * GBN;
    const int nit = (K + GBK - 1) / GBK;

    __shared__ __align__(16) float As[GBK][GBM + 4];
    __shared__ __align__(16) float Bs[GBK][GBN + 4];

    const int tid = threadIdx.x;
    const int tx = tid & 15;
    const int ty = tid >> 4;

    const int lr  = tid >> 1;
    const int lkq = (tid & 1) * 8;

    unsigned long long acc[8][2];
#pragma unroll
    for (int i = 0; i < 8; i++) { acc[i][0] = 0ull; acc[i][1] = 0ull; }

    for (int it = 0; it < nit; ++it) {
        const int k0 = it * GBK;
        {
            const int m = m0 + lr;
            const float* p = A + (size_t)m * K + k0 + lkq;
#pragma unroll
            for (int q = 0; q < 8; q++) {
                const int k = k0 + lkq + q;
                As[lkq + q][lr] = (m < M && k < K) ? __ldg(p + q) : 0.f;
            }
        }
        {
            const int nn = n0 + lr;
            const float* p = B + (size_t)nn * K + k0 + lkq;
#pragma unroll
            for (int q = 0; q < 8; q++) {
                const int k = k0 + lkq + q;
                Bs[lkq + q][lr] = (nn < N && k < K) ? __ldg(p + q) : 0.f;
            }
        }
        __syncthreads();
#pragma unroll
        for (int kk = 0; kk < GBK; kk++) {
            const float4 a0 = *(const float4*)&As[kk][ty * 8];
            const float4 a1 = *(const float4*)&As[kk][ty * 8 + 4];
            const ulonglong2 bv = *(const ulonglong2*)&Bs[kk][tx * 4];
            const float a[8] = { a0.x, a0.y, a0.z, a0.w, a1.x, a1.y, a1.z, a1.w };
#pragma unroll
            for (int mi = 0; mi < 8; mi++) {
                const unsigned long long av = bcast2(a[mi]);
                ffma2u(acc[mi][0], av, bv.x);
                ffma2u(acc[mi][1], av, bv.y);
            }
        }
        __syncthreads();
    }

#pragma unroll
    for (int mi = 0; mi < 8; mi++) {
        const int m = m0 + ty * 8 + mi;
        if (m >= M) continue;
        float* crow = C + (size_t)m * ldc;
#pragma unroll
        for (int nj = 0; nj < 2; nj++) {
            const float2 v = unpack2(acc[mi][nj]);
            const int n = n0 + tx * 4 + nj * 2;
            if (n < N) {
                float o = v.x + bias[n];
                if (relu) o = o > 0.f ? o : 0.f;
                crow[n] = o;
            }
            if (n + 1 < N) {
                float o = v.y + bias[n + 1];
                if (relu) o = o > 0.f ? o : 0.f;
                crow[n + 1] = o;
            }
        }
    }
}

// ---------------- launch ----------------
extern "C" void kernel_launch(void* const* d_in, const int* in_sizes, int n_in,
                              void* d_out, int out_size)
{
    const float* x          = (const float*)d_in[0];
    const float* rois       = (const float*)d_in[1];
    const float* w_col_max  = (const float*)d_in[2];
    const float* b_col_max  = (const float*)d_in[3];
    const float* w_col      = (const float*)d_in[4];
    const float* b_col      = (const float*)d_in[5];
    const float* w_row_max  = (const float*)d_in[6];
    const float* b_row_max  = (const float*)d_in[7];
    const float* w_row      = (const float*)d_in[8];
    const float* b_row      = (const float*)d_in[9];
    const float* w_fc1      = (const float*)d_in[10];
    const float* b_fc1      = (const float*)d_in[11];
    const float* w_score    = (const float*)d_in[12];
    const float* b_score    = (const float*)d_in[13];
    const float* w_loc      = (const float*)d_in[14];
    const float* b_loc      = (const float*)d_in[15];
    float* out = (float*)d_out;

    __half *XP, *TP0, *TP1, *wt1, *wt2;
    float *p1, *h0, *h1, *h, *flat, *fc1;
    cudaGetSymbolAddress((void**)&XP,   g_XP);
    cudaGetSymbolAddress((void**)&TP0,  g_TP0);
    cudaGetSymbolAddress((void**)&TP1,  g_TP1);
    cudaGetSymbolAddress((void**)&wt1,  g_wt1);
    cudaGetSymbolAddress((void**)&wt2,  g_wt2);
    cudaGetSymbolAddress((void**)&p1,   g_p1);
    cudaGetSymbolAddress((void**)&h0,   g_h0);
    cudaGetSymbolAddress((void**)&h1,   g_h1);
    cudaGetSymbolAddress((void**)&h,    g_h);
    cudaGetSymbolAddress((void**)&flat, g_flat);
    cudaGetSymbolAddress((void**)&fc1,  g_fc1);

    cudaFuncSetAttribute(conv_mma, cudaFuncAttributeMaxDynamicSharedMemorySize, CONV_SMEM);

    // prep: zero padded buffers (pads must be zero; valid regions overwritten below)
    {
        const int na = PROWS * 2048 * 2 / 16;   // XP bytes/16
        const int nb = PROWS * 256  * 2 / 16;   // TP bytes/16
        zero_fill<<<(na + 255) / 256, 256>>>((uint4*)XP, na, (uint4*)TP0, nb, (uint4*)TP1, nb);
    }
    // transpose x -> XP
    xpose<<<dim3(2048 / 64, (HW + 63) / 64), 256>>>(x, (__half2*)XP);
    // weights -> [t][oc][c] half
    wtrans<<<dim3(OCPAD1, 2048 / 128), 256>>>(w_col_max, wt1, 256, OCPAD1, 2048);
    wtrans<<<dim3(OCPAD1, 2048 / 128), 256>>>(w_row_max, wt1 + (size_t)TAPS * OCPAD1 * 2048, 256, OCPAD1, 2048);
    wtrans<<<dim3(OCPAD2, 256 / 128), 256>>>(w_col, wt2, OUTDIM, OCPAD2, 256);
    wtrans<<<dim3(OCPAD2, 256 / 128), 256>>>(w_row, wt2 + (size_t)TAPS * OCPAD2 * 256, OUTDIM, OCPAD2, 256);

    // conv1: branch0 = w_col_max (15x1, H-shift step 64), branch1 = w_row_max (1x15, W-shift step 1)
    {
        dim3 grid((HW + 127) / 128, OCPAD1 / 128, 2 * S1);   // 15 x 2 x 4 = 120
        conv_mma<<<grid, 256, CONV_SMEM>>>(
            XP, XP,
            wt1, wt1 + (size_t)TAPS * OCPAD1 * 2048,
            p1, p1 + (size_t)S1 * OCPAD1 * HW,
            64, 1, 2048, 2048 / 32 / S1, OCPAD1, S1);
    }
    // combine1: sum splits + bias -> TP0/TP1 (padded half)
    combine1<<<dim3(OCPAD1 / 64, (HW + 63) / 64, 2), 256>>>(p1, b_col_max, b_row_max,
                                                            (__half2*)TP0, (__half2*)TP1);
    // conv2: branch0 = TP0 with w_col (1x15, W step 1), branch1 = TP1 with w_row (15x1, H step 64)
    {
        dim3 grid((HW + 127) / 128, OCPAD2 / 128, 2);        // 15 x 4 x 2 = 120
        conv_mma<<<grid, 256, CONV_SMEM>>>(
            TP0, TP1,
            wt2, wt2 + (size_t)TAPS * OCPAD2 * 256,
            h0, h1,
            1, 64, 256, 256 / 32, OCPAD2, 1);
    }
    // h = relu(h0 + h1 + b_col + b_row)
    {
        const int n = OUTDIM * (HW / 4);
        combine2<<<(n + 255) / 256, 256>>>((const float4*)h0, (const float4*)h1, b_col, b_row, (float4*)h);
    }
    // ROI pool -> flat [512, 490]
    {
        const int n = NROIS * OUTDIM;
        roi_pool<<<(n + 255) / 256, 256>>>(h, rois, flat);
    }
    // fc1 = relu(flat @ w_fc1^T + b_fc1)   [512, 2048]
    {
        dim3 grid(2048 / GBN, NROIS / GBM);
        gemm_tn<<<grid, 128>>>(flat, w_fc1, b_fc1, fc1, NROIS, 2048, OUTDIM, 2048, 1);
    }
    // roi_cls_locs = fc1 @ w_loc^T + b_loc   [512, 324]
    {
        dim3 grid((324 + GBN - 1) / GBN, NROIS / GBM);
        gemm_tn<<<grid, 128>>>(fc1, w_loc, b_loc, out, NROIS, 324, 2048, 324, 0);
    }
    // roi_scores = fc1 @ w_score^T + b_score [512, 81]
    {
        dim3 grid((81 + GBN - 1) / GBN, NROIS / GBM);
        gemm_tn<<<grid, 128>>>(fc1, w_score, b_score, out + NROIS * 324, NROIS, 81, 2048, 81, 0);
    }
}